// round 10
// baseline (speedup 1.0000x reference)
#include <cuda_runtime.h>
#include <math.h>
#include <stdint.h>

#define NN    50000
#define FH    128      // H*C
#define NH    4
#define EMAX  800000
#define NEG   0.2f
#define NBMAX 256      // >= ceil(NN/256) scan blocks
#define LOG2E 1.44269504088896f

// ---------------- scratch (static device globals; no runtime alloc) --------
__device__ float  g_xp[NN * FH];         // projected features fp32 [N][128]
__device__ float  g_asrc[NN * NH];       // prescaled by log2e
__device__ float  g_adst[NN * NH];       // prescaled by log2e
__device__ int    g_deg[NN];             // real-edge counts; re-zeroed in scan
__device__ int    g_ord[EMAX];           // per-edge ordinal within its dst row
__device__ int    g_rowptr[NN + 1];
__device__ int    g_bval[NBMAX];
__device__ volatile int g_bflag[NBMAX];
__device__ int    g_csr[EMAX + NN];

// ---------------- helpers ---------------------------------------------------
__device__ __forceinline__ void f2tf32x2(float f, uint32_t& hi, uint32_t& lo) {
    asm("cvt.rna.tf32.f32 %0, %1;" : "=r"(hi) : "f"(f));
    float d = f - __uint_as_float(hi);
    asm("cvt.rna.tf32.f32 %0, %1;" : "=r"(lo) : "f"(d));
}

__device__ __forceinline__ void mma_tf32(float* c, const uint32_t* a, const uint32_t* b) {
    asm volatile(
        "mma.sync.aligned.m16n8k8.row.col.f32.tf32.tf32.f32 "
        "{%0,%1,%2,%3}, {%4,%5,%6,%7}, {%8,%9}, {%0,%1,%2,%3};"
        : "+f"(c[0]), "+f"(c[1]), "+f"(c[2]), "+f"(c[3])
        : "r"(a[0]), "r"(a[1]), "r"(a[2]), "r"(a[3]), "r"(b[0]), "r"(b[1]));
}

__device__ __forceinline__ void ffma2(unsigned long long& acc, unsigned long long v,
                                      unsigned long long w2) {
    asm("fma.rn.f32x2 %0, %1, %2, %0;" : "+l"(acc) : "l"(v), "l"(w2));
}

__device__ __forceinline__ float ex2(float a) {
    float r;
    asm("ex2.approx.f32 %0, %1;" : "=f"(r) : "f"(a));
    return r;
}

// ---------------- histogram: per-edge ordinal + scan-state reset ------------
__global__ void k_hist(const int* __restrict__ dst, int E) {
    int e = blockIdx.x * blockDim.x + threadIdx.x;
    if (blockIdx.x == 0 && threadIdx.x < NBMAX) g_bflag[threadIdx.x] = 0;
    if (e < E) {
        int d = __ldcs(dst + e);
        g_ord[e] = atomicAdd(&g_deg[d], 1);
    }
}

// ---------------- GEMM: xp = x @ W^T via 3xTF32 tensor cores ----------------
#define XP 20
#define WP 136
__global__ __launch_bounds__(256) void k_gemm(
    const float* __restrict__ x, const float* __restrict__ W,
    const float* __restrict__ attS, const float* __restrict__ attD, int n)
{
    __shared__ float xsh[128 * XP], xsl[128 * XP];
    __shared__ float wth[16 * WP],  wtl[16 * WP];
    __shared__ float sAttS[128], sAttD[128];
    __shared__ float sAs[128 * 4], sAd[128 * 4];

    int t = threadIdx.x;
    // prescale by log2e: exp(leaky(z)) == exp2(leaky(z*log2e)) (leaky pos-homog.)
    if (t < 128) { sAttS[t] = attS[t] * LOG2E; sAttD[t] = attD[t] * LOG2E; }

    int row0 = blockIdx.x * 128;
    int wid = t >> 5, lane = t & 31;
    int wm = wid >> 1, wn = wid & 1;
    int g = lane >> 2, q4 = lane & 3;

    float acc[2][8][4];
#pragma unroll
    for (int mt = 0; mt < 2; mt++)
#pragma unroll
        for (int nt = 0; nt < 8; nt++)
#pragma unroll
            for (int c = 0; c < 4; c++) acc[mt][nt][c] = 0.f;

    for (int kc = 0; kc < 128; kc += 16) {
#pragma unroll
        for (int j = 0; j < 2; j++) {
            int idx = t + 256 * j;
            int r = idx >> 2, q = idx & 3;
            float4 v = make_float4(0.f, 0.f, 0.f, 0.f);
            if (row0 + r < n) v = *(const float4*)(x + (size_t)(row0 + r) * 128 + kc + q * 4);
            uint32_t h0, l0, h1, l1, h2, l2, h3, l3;
            f2tf32x2(v.x, h0, l0); f2tf32x2(v.y, h1, l1);
            f2tf32x2(v.z, h2, l2); f2tf32x2(v.w, h3, l3);
            float* ph = xsh + r * XP + q * 4;
            float* pl = xsl + r * XP + q * 4;
            ph[0] = __uint_as_float(h0); ph[1] = __uint_as_float(h1);
            ph[2] = __uint_as_float(h2); ph[3] = __uint_as_float(h3);
            pl[0] = __uint_as_float(l0); pl[1] = __uint_as_float(l1);
            pl[2] = __uint_as_float(l2); pl[3] = __uint_as_float(l3);
        }
#pragma unroll
        for (int j = 0; j < 2; j++) {
            int idx = t + 256 * j;
            int oc = idx >> 2, q = idx & 3;
            float4 v = *(const float4*)(W + (size_t)oc * 128 + kc + q * 4);
            uint32_t h0, l0, h1, l1, h2, l2, h3, l3;
            f2tf32x2(v.x, h0, l0); f2tf32x2(v.y, h1, l1);
            f2tf32x2(v.z, h2, l2); f2tf32x2(v.w, h3, l3);
            wth[(q * 4 + 0) * WP + oc] = __uint_as_float(h0);
            wth[(q * 4 + 1) * WP + oc] = __uint_as_float(h1);
            wth[(q * 4 + 2) * WP + oc] = __uint_as_float(h2);
            wth[(q * 4 + 3) * WP + oc] = __uint_as_float(h3);
            wtl[(q * 4 + 0) * WP + oc] = __uint_as_float(l0);
            wtl[(q * 4 + 1) * WP + oc] = __uint_as_float(l1);
            wtl[(q * 4 + 2) * WP + oc] = __uint_as_float(l2);
            wtl[(q * 4 + 3) * WP + oc] = __uint_as_float(l3);
        }
        __syncthreads();

#pragma unroll
        for (int kk = 0; kk < 16; kk += 8) {
            uint32_t ah[2][4], al[2][4];
#pragma unroll
            for (int mt = 0; mt < 2; mt++) {
                int r = wm * 32 + mt * 16 + g;
                int b0 = r * XP + kk + q4;
                ah[mt][0] = __float_as_uint(xsh[b0]);
                ah[mt][1] = __float_as_uint(xsh[b0 + 8 * XP]);
                ah[mt][2] = __float_as_uint(xsh[b0 + 4]);
                ah[mt][3] = __float_as_uint(xsh[b0 + 8 * XP + 4]);
                al[mt][0] = __float_as_uint(xsl[b0]);
                al[mt][1] = __float_as_uint(xsl[b0 + 8 * XP]);
                al[mt][2] = __float_as_uint(xsl[b0 + 4]);
                al[mt][3] = __float_as_uint(xsl[b0 + 8 * XP + 4]);
            }
#pragma unroll
            for (int nt = 0; nt < 8; nt++) {
                int col = wn * 64 + nt * 8 + g;
                int kb = (kk + q4) * WP + col;
                uint32_t bh[2], bl[2];
                bh[0] = __float_as_uint(wth[kb]);
                bh[1] = __float_as_uint(wth[kb + 4 * WP]);
                bl[0] = __float_as_uint(wtl[kb]);
                bl[1] = __float_as_uint(wtl[kb + 4 * WP]);
#pragma unroll
                for (int mt = 0; mt < 2; mt++) {
                    mma_tf32(acc[mt][nt], ah[mt], bh);
                    mma_tf32(acc[mt][nt], ah[mt], bl);
                    mma_tf32(acc[mt][nt], al[mt], bh);
                }
            }
        }
        __syncthreads();
    }

#pragma unroll
    for (int mt = 0; mt < 2; mt++) {
#pragma unroll
        for (int half = 0; half < 2; half++) {
            int rl = wm * 32 + mt * 16 + half * 8 + g;
            int r = row0 + rl;
            float ps0 = 0.f, pd0 = 0.f, ps1 = 0.f, pd1 = 0.f;
#pragma unroll
            for (int nt = 0; nt < 8; nt++) {
                int cbase = wn * 64 + nt * 8 + q4 * 2;
                float v0 = acc[mt][nt][half * 2 + 0];
                float v1 = acc[mt][nt][half * 2 + 1];
                float as0 = sAttS[cbase], as1 = sAttS[cbase + 1];
                float ad0 = sAttD[cbase], ad1 = sAttD[cbase + 1];
                if (nt < 4) { ps0 += v0 * as0 + v1 * as1; pd0 += v0 * ad0 + v1 * ad1; }
                else        { ps1 += v0 * as0 + v1 * as1; pd1 += v0 * ad0 + v1 * ad1; }
                if (r < n)
                    *(float2*)(g_xp + (size_t)r * 128 + cbase) = make_float2(v0, v1);
            }
            ps0 += __shfl_xor_sync(0xffffffffu, ps0, 1); ps0 += __shfl_xor_sync(0xffffffffu, ps0, 2);
            ps1 += __shfl_xor_sync(0xffffffffu, ps1, 1); ps1 += __shfl_xor_sync(0xffffffffu, ps1, 2);
            pd0 += __shfl_xor_sync(0xffffffffu, pd0, 1); pd0 += __shfl_xor_sync(0xffffffffu, pd0, 2);
            pd1 += __shfl_xor_sync(0xffffffffu, pd1, 1); pd1 += __shfl_xor_sync(0xffffffffu, pd1, 2);
            if (q4 == 0) {
                sAs[rl * 4 + wn * 2 + 0] = ps0;
                sAs[rl * 4 + wn * 2 + 1] = ps1;
                sAd[rl * 4 + wn * 2 + 0] = pd0;
                sAd[rl * 4 + wn * 2 + 1] = pd1;
            }
        }
    }
    __syncthreads();
    if (t < 128 && row0 + t < n) {
        *(float4*)(g_asrc + (size_t)(row0 + t) * 4) = *(const float4*)(sAs + t * 4);
        *(float4*)(g_adst + (size_t)(row0 + t) * 4) = *(const float4*)(sAd + t * 4);
    }
}

// ---------------- scan: rowptr from deg (+1 self loop), lookback ------------
__global__ __launch_bounds__(256) void k_scan(int n, int nscan) {
    __shared__ int s[256];
    int t = threadIdx.x, b = blockIdx.x, i = b * 256 + t;
    int v = 0;
    if (i < n) { v = g_deg[i] + 1; g_deg[i] = 0; }
    s[t] = v;
    __syncthreads();
#pragma unroll
    for (int off = 1; off < 256; off <<= 1) {
        int u = (t >= off) ? s[t - off] : 0;
        __syncthreads();
        s[t] += u;
        __syncthreads();
    }
    int incl = s[t];
    int agg  = s[255];
    if (t == 255) {
        g_bval[b] = agg;
        __threadfence();
        g_bflag[b] = 1;
    }
    int part = 0;
    for (int j = t; j < b; j += 256) {
        while (g_bflag[j] == 0) { }
        part += *(volatile int*)&g_bval[j];
    }
    __syncthreads();
    s[t] = part;
    __syncthreads();
#pragma unroll
    for (int off = 128; off > 0; off >>= 1) {
        if (t < off) s[t] += s[t + off];
        __syncthreads();
    }
    int excl0 = s[0];
    if (i < n) g_rowptr[i] = excl0 + incl - v;
    if (b == nscan - 1 && t == 255) g_rowptr[n] = excl0 + agg;
}

// ---------------- scatter: atomic-free, 4 strided elems/thread (MLP=4) ------
__global__ void k_scatter(const int* __restrict__ src, const int* __restrict__ dst,
                          int E, int n, int S) {
    int tid = blockIdx.x * blockDim.x + threadIdx.x;
    int total = E + n;

    int e[4], d[4], o[4];
    bool isE[4], ok[4];
#pragma unroll
    for (int k = 0; k < 4; k++) {
        e[k] = tid + k * S;
        ok[k] = e[k] < total;
        isE[k] = e[k] < E;
    }
#pragma unroll
    for (int k = 0; k < 4; k++)
        if (isE[k]) { d[k] = __ldcs(dst + e[k]); }
#pragma unroll
    for (int k = 0; k < 4; k++)
        if (isE[k]) { o[k] = __ldcs(g_ord + e[k]); }

    int p[4];
#pragma unroll
    for (int k = 0; k < 4; k++) {
        if (isE[k])      p[k] = g_rowptr[d[k]] + o[k];
        else if (ok[k])  p[k] = g_rowptr[e[k] - E + 1] - 1;   // self loop slot
    }
    int v[4];
#pragma unroll
    for (int k = 0; k < 4; k++) {
        if (isE[k])      v[k] = __ldcs(src + e[k]);
        else if (ok[k])  v[k] = e[k] - E;
    }
#pragma unroll
    for (int k = 0; k < 4; k++)
        if (ok[k]) g_csr[p[k]] = v[k];
}

// ---------------- aggregation: HALF-warp per destination node ---------------
// 16 lanes per node, 8 output cols per lane; scalar per-edge work (csr/asrc
// loads, leaky, ex2, den) amortized over 2 nodes per warp instruction.
__global__ __launch_bounds__(256) void k_agg(
    const float* __restrict__ bias, float* __restrict__ out, int n)
{
    int warp = (blockIdx.x * blockDim.x + threadIdx.x) >> 5;
    int lane = threadIdx.x & 31;
    int half = lane >> 4;
    int hl   = lane & 15;
    int nd0  = warp * 2;
    if (nd0 >= n) return;
    int nd   = nd0 + half;
    bool ndv = nd < n;
    int ndc  = ndv ? nd : n - 1;

    int h = hl >> 2;                         // head (4 lanes per head)
    int colbase = h * 32 + (hl & 3) * 8;     // 8 cols per lane

    int begin = g_rowptr[ndc];
    int len   = ndv ? (g_rowptr[ndc + 1] - begin) : 0;
    int lenO  = __shfl_xor_sync(0xffffffffu, len, 16);
    int lmax  = max(len, lenO);
    float adh = g_adst[ndc * 4 + h];

    unsigned long long a0 = 0ull, a1 = 0ull, a2 = 0ull, a3 = 0ull;
    float den = 0.f;
    const char* xpb = (const char*)g_xp + colbase * 4;

#define AGG_BODY(I)                                                            \
    {                                                                          \
        int ii = (I);                                                          \
        int idx = begin + min(ii, len - 1);                                    \
        int s = __ldcs(g_csr + idx);                                           \
        float a = g_asrc[s * 4 + h] + adh;                                     \
        a = fmaxf(a, NEG * a);                                                 \
        float w = ex2(a);                                                      \
        w = (ii < len) ? w : 0.f;                                              \
        const ulonglong2* row = (const ulonglong2*)(xpb + (unsigned)s * 512u); \
        ulonglong2 u0 = row[0];                                                \
        ulonglong2 u1 = row[1];                                                \
        unsigned long long ww;                                                 \
        asm("mov.b64 %0, {%1, %1};" : "=l"(ww) : "f"(w));                      \
        ffma2(a0, u0.x, ww); ffma2(a1, u0.y, ww);                              \
        ffma2(a2, u1.x, ww); ffma2(a3, u1.y, ww);                              \
        den += w;                                                              \
    }

    int i = 0;
    for (; i + 2 <= lmax; i += 2) { AGG_BODY(i) AGG_BODY(i + 1) }
    if (i < lmax) { AGG_BODY(i) }
#undef AGG_BODY

    float f0, f1, f2, f3, f4, f5, f6, f7;
    asm("mov.b64 {%0, %1}, %2;" : "=f"(f0), "=f"(f1) : "l"(a0));
    asm("mov.b64 {%0, %1}, %2;" : "=f"(f2), "=f"(f3) : "l"(a1));
    asm("mov.b64 {%0, %1}, %2;" : "=f"(f4), "=f"(f5) : "l"(a2));
    asm("mov.b64 {%0, %1}, %2;" : "=f"(f6), "=f"(f7) : "l"(a3));

    float inv = 1.0f / (den + 1e-16f);
    float4 b0 = *(const float4*)(bias + colbase);
    float4 b1 = *(const float4*)(bias + colbase + 4);
    float o0 = f0 * inv + b0.x, o1 = f1 * inv + b0.y;
    float o2 = f2 * inv + b0.z, o3 = f3 * inv + b0.w;
    float o4 = f4 * inv + b1.x, o5 = f5 * inv + b1.y;
    float o6 = f6 * inv + b1.z, o7 = f7 * inv + b1.w;
    o0 = o0 > 0.f ? o0 : (__expf(o0) - 1.f);
    o1 = o1 > 0.f ? o1 : (__expf(o1) - 1.f);
    o2 = o2 > 0.f ? o2 : (__expf(o2) - 1.f);
    o3 = o3 > 0.f ? o3 : (__expf(o3) - 1.f);
    o4 = o4 > 0.f ? o4 : (__expf(o4) - 1.f);
    o5 = o5 > 0.f ? o5 : (__expf(o5) - 1.f);
    o6 = o6 > 0.f ? o6 : (__expf(o6) - 1.f);
    o7 = o7 > 0.f ? o7 : (__expf(o7) - 1.f);

    if (ndv) {
        float* op = out + (size_t)nd * 128 + colbase;
        *(float4*)(op)     = make_float4(o0, o1, o2, o3);
        *(float4*)(op + 4) = make_float4(o4, o5, o6, o7);
    }
}

// ---------------- launch: GEMM overlapped with CSR chain --------------------
extern "C" void kernel_launch(void* const* d_in, const int* in_sizes, int n_in,
                              void* d_out, int out_size)
{
    const float* x    = (const float*)d_in[0];
    const float* W    = (const float*)d_in[1];
    const float* attS = (const float*)d_in[2];
    const float* attD = (const float*)d_in[3];
    const float* bias = (const float*)d_in[4];
    const int*   ei   = (const int*)d_in[5];

    int n = in_sizes[0] / FH;        // 50000
    int E = in_sizes[5] / 2;         // 800000
    const int* src = ei;
    const int* dst = ei + E;

    int nscan  = (n + 255) / 256;                    // 196
    int nscat  = (E + n + 1023) / 1024;              // 4 elems/thread
    int S      = nscat * 256;
    int nwarp  = (n + 1) / 2;                        // 2 nodes per warp

    // host-side resources, created once (host objects only; no device memory)
    static cudaStream_t s_side = nullptr;
    static cudaEvent_t  ev_fork = nullptr, ev_join = nullptr;
    if (s_side == nullptr) {
        cudaStreamCreateWithFlags(&s_side, cudaStreamNonBlocking);
        cudaEventCreateWithFlags(&ev_fork, cudaEventDisableTiming);
        cudaEventCreateWithFlags(&ev_join, cudaEventDisableTiming);
    }

    // fork: GEMM on side stream, CSR chain on main stream — independent work
    cudaEventRecord(ev_fork, 0);
    cudaStreamWaitEvent(s_side, ev_fork, 0);
    k_gemm<<<(n + 127) / 128, 256, 0, s_side>>>(x, W, attS, attD, n);
    cudaEventRecord(ev_join, s_side);

    k_hist<<<(E + 255) / 256, 256>>>(dst, E);
    k_scan<<<nscan, 256>>>(n, nscan);
    k_scatter<<<nscat, 256>>>(src, dst, E, n, S);

    // join: aggregation needs both GEMM outputs and CSR
    cudaStreamWaitEvent(0, ev_join, 0);
    k_agg<<<(nwarp * 32 + 255) / 256, 256>>>(bias, (float*)d_out, n);
}

// round 11
// speedup vs baseline: 1.0566x; 1.0566x over previous
#include <cuda_runtime.h>
#include <math.h>
#include <stdint.h>

#define NN    50000
#define FH    128      // H*C
#define NH    4
#define EMAX  800000
#define NEG   0.2f
#define NBMAX 256      // >= ceil(NN/256) scan blocks
#define LOG2E 1.44269504088896f

// ---------------- scratch (static device globals; no runtime alloc) --------
__device__ float  g_xp[NN * FH];         // projected features fp32 [N][128]
__device__ float  g_asrc[NN * NH];       // prescaled by log2e
__device__ float  g_adst[NN * NH];       // prescaled by log2e
__device__ int    g_deg[NN];             // real-edge counts; re-zeroed in scan
__device__ int    g_ord[EMAX];           // per-edge ordinal within its dst row
__device__ int    g_rowptr[NN + 1];
__device__ int    g_bval[NBMAX];
__device__ volatile int g_bflag[NBMAX];
__device__ int    g_hdone, g_sdone;      // phase counters; reset by k_agg
__device__ int    g_csr[EMAX + NN];

// ---------------- helpers ---------------------------------------------------
__device__ __forceinline__ void f2tf32x2(float f, uint32_t& hi, uint32_t& lo) {
    asm("cvt.rna.tf32.f32 %0, %1;" : "=r"(hi) : "f"(f));
    float d = f - __uint_as_float(hi);
    asm("cvt.rna.tf32.f32 %0, %1;" : "=r"(lo) : "f"(d));
}

__device__ __forceinline__ void mma_tf32(float* c, const uint32_t* a, const uint32_t* b) {
    asm volatile(
        "mma.sync.aligned.m16n8k8.row.col.f32.tf32.tf32.f32 "
        "{%0,%1,%2,%3}, {%4,%5,%6,%7}, {%8,%9}, {%0,%1,%2,%3};"
        : "+f"(c[0]), "+f"(c[1]), "+f"(c[2]), "+f"(c[3])
        : "r"(a[0]), "r"(a[1]), "r"(a[2]), "r"(a[3]), "r"(b[0]), "r"(b[1]));
}

__device__ __forceinline__ void ffma2(unsigned long long& acc, unsigned long long v,
                                      unsigned long long w2) {
    asm("fma.rn.f32x2 %0, %1, %2, %0;" : "+l"(acc) : "l"(v), "l"(w2));
}

__device__ __forceinline__ float ex2(float a) {
    float r;
    asm("ex2.approx.f32 %0, %1;" : "=f"(r) : "f"(a));
    return r;
}

// ---------------- GEMM: xp = x @ W^T via 3xTF32 tensor cores ----------------
#define XP 20
#define WP 136
__global__ __launch_bounds__(256) void k_gemm(
    const float* __restrict__ x, const float* __restrict__ W,
    const float* __restrict__ attS, const float* __restrict__ attD, int n)
{
    __shared__ float xsh[128 * XP], xsl[128 * XP];
    __shared__ float wth[16 * WP],  wtl[16 * WP];
    __shared__ float sAttS[128], sAttD[128];
    __shared__ float sAs[128 * 4], sAd[128 * 4];

    int t = threadIdx.x;
    // prescale by log2e: exp(leaky(z)) == exp2(leaky(z*log2e)) (leaky pos-homog.)
    if (t < 128) { sAttS[t] = attS[t] * LOG2E; sAttD[t] = attD[t] * LOG2E; }

    int row0 = blockIdx.x * 128;
    int wid = t >> 5, lane = t & 31;
    int wm = wid >> 1, wn = wid & 1;
    int g = lane >> 2, q4 = lane & 3;

    float acc[2][8][4];
#pragma unroll
    for (int mt = 0; mt < 2; mt++)
#pragma unroll
        for (int nt = 0; nt < 8; nt++)
#pragma unroll
            for (int c = 0; c < 4; c++) acc[mt][nt][c] = 0.f;

    for (int kc = 0; kc < 128; kc += 16) {
#pragma unroll
        for (int j = 0; j < 2; j++) {
            int idx = t + 256 * j;
            int r = idx >> 2, q = idx & 3;
            float4 v = make_float4(0.f, 0.f, 0.f, 0.f);
            if (row0 + r < n) v = *(const float4*)(x + (size_t)(row0 + r) * 128 + kc + q * 4);
            uint32_t h0, l0, h1, l1, h2, l2, h3, l3;
            f2tf32x2(v.x, h0, l0); f2tf32x2(v.y, h1, l1);
            f2tf32x2(v.z, h2, l2); f2tf32x2(v.w, h3, l3);
            float* ph = xsh + r * XP + q * 4;
            float* pl = xsl + r * XP + q * 4;
            ph[0] = __uint_as_float(h0); ph[1] = __uint_as_float(h1);
            ph[2] = __uint_as_float(h2); ph[3] = __uint_as_float(h3);
            pl[0] = __uint_as_float(l0); pl[1] = __uint_as_float(l1);
            pl[2] = __uint_as_float(l2); pl[3] = __uint_as_float(l3);
        }
#pragma unroll
        for (int j = 0; j < 2; j++) {
            int idx = t + 256 * j;
            int oc = idx >> 2, q = idx & 3;
            float4 v = *(const float4*)(W + (size_t)oc * 128 + kc + q * 4);
            uint32_t h0, l0, h1, l1, h2, l2, h3, l3;
            f2tf32x2(v.x, h0, l0); f2tf32x2(v.y, h1, l1);
            f2tf32x2(v.z, h2, l2); f2tf32x2(v.w, h3, l3);
            wth[(q * 4 + 0) * WP + oc] = __uint_as_float(h0);
            wth[(q * 4 + 1) * WP + oc] = __uint_as_float(h1);
            wth[(q * 4 + 2) * WP + oc] = __uint_as_float(h2);
            wth[(q * 4 + 3) * WP + oc] = __uint_as_float(h3);
            wtl[(q * 4 + 0) * WP + oc] = __uint_as_float(l0);
            wtl[(q * 4 + 1) * WP + oc] = __uint_as_float(l1);
            wtl[(q * 4 + 2) * WP + oc] = __uint_as_float(l2);
            wtl[(q * 4 + 3) * WP + oc] = __uint_as_float(l3);
        }
        __syncthreads();

#pragma unroll
        for (int kk = 0; kk < 16; kk += 8) {
            uint32_t ah[2][4], al[2][4];
#pragma unroll
            for (int mt = 0; mt < 2; mt++) {
                int r = wm * 32 + mt * 16 + g;
                int b0 = r * XP + kk + q4;
                ah[mt][0] = __float_as_uint(xsh[b0]);
                ah[mt][1] = __float_as_uint(xsh[b0 + 8 * XP]);
                ah[mt][2] = __float_as_uint(xsh[b0 + 4]);
                ah[mt][3] = __float_as_uint(xsh[b0 + 8 * XP + 4]);
                al[mt][0] = __float_as_uint(xsl[b0]);
                al[mt][1] = __float_as_uint(xsl[b0 + 8 * XP]);
                al[mt][2] = __float_as_uint(xsl[b0 + 4]);
                al[mt][3] = __float_as_uint(xsl[b0 + 8 * XP + 4]);
            }
#pragma unroll
            for (int nt = 0; nt < 8; nt++) {
                int col = wn * 64 + nt * 8 + g;
                int kb = (kk + q4) * WP + col;
                uint32_t bh[2], bl[2];
                bh[0] = __float_as_uint(wth[kb]);
                bh[1] = __float_as_uint(wth[kb + 4 * WP]);
                bl[0] = __float_as_uint(wtl[kb]);
                bl[1] = __float_as_uint(wtl[kb + 4 * WP]);
#pragma unroll
                for (int mt = 0; mt < 2; mt++) {
                    mma_tf32(acc[mt][nt], ah[mt], bh);
                    mma_tf32(acc[mt][nt], ah[mt], bl);
                    mma_tf32(acc[mt][nt], al[mt], bh);
                }
            }
        }
        __syncthreads();
    }

#pragma unroll
    for (int mt = 0; mt < 2; mt++) {
#pragma unroll
        for (int half = 0; half < 2; half++) {
            int rl = wm * 32 + mt * 16 + half * 8 + g;
            int r = row0 + rl;
            float ps0 = 0.f, pd0 = 0.f, ps1 = 0.f, pd1 = 0.f;
#pragma unroll
            for (int nt = 0; nt < 8; nt++) {
                int cbase = wn * 64 + nt * 8 + q4 * 2;
                float v0 = acc[mt][nt][half * 2 + 0];
                float v1 = acc[mt][nt][half * 2 + 1];
                float as0 = sAttS[cbase], as1 = sAttS[cbase + 1];
                float ad0 = sAttD[cbase], ad1 = sAttD[cbase + 1];
                if (nt < 4) { ps0 += v0 * as0 + v1 * as1; pd0 += v0 * ad0 + v1 * ad1; }
                else        { ps1 += v0 * as0 + v1 * as1; pd1 += v0 * ad0 + v1 * ad1; }
                if (r < n)
                    *(float2*)(g_xp + (size_t)r * 128 + cbase) = make_float2(v0, v1);
            }
            ps0 += __shfl_xor_sync(0xffffffffu, ps0, 1); ps0 += __shfl_xor_sync(0xffffffffu, ps0, 2);
            ps1 += __shfl_xor_sync(0xffffffffu, ps1, 1); ps1 += __shfl_xor_sync(0xffffffffu, ps1, 2);
            pd0 += __shfl_xor_sync(0xffffffffu, pd0, 1); pd0 += __shfl_xor_sync(0xffffffffu, pd0, 2);
            pd1 += __shfl_xor_sync(0xffffffffu, pd1, 1); pd1 += __shfl_xor_sync(0xffffffffu, pd1, 2);
            if (q4 == 0) {
                sAs[rl * 4 + wn * 2 + 0] = ps0;
                sAs[rl * 4 + wn * 2 + 1] = ps1;
                sAd[rl * 4 + wn * 2 + 0] = pd0;
                sAd[rl * 4 + wn * 2 + 1] = pd1;
            }
        }
    }
    __syncthreads();
    if (t < 128 && row0 + t < n) {
        *(float4*)(g_asrc + (size_t)(row0 + t) * 4) = *(const float4*)(sAs + t * 4);
        *(float4*)(g_adst + (size_t)(row0 + t) * 4) = *(const float4*)(sAd + t * 4);
    }
}

// ---------------- fused CSR build: hist | scan | scatter phases -------------
// Block ranges: [0,nhist) hist, [nhist,nhist+nscan) scan, rest scatter.
// Every wait targets strictly-lower block IDs (monotone dispatch => no deadlock).
// Only thread 0 of a waiting block polls (no LTS polling storm).
__global__ __launch_bounds__(256) void k_csr(
    const int* __restrict__ src, const int* __restrict__ dst,
    int n, int E, int nhist, int nscan)
{
    __shared__ int s[256];
    int t = threadIdx.x, b = blockIdx.x;

    if (b < nhist) {
        // ---- phase 1: histogram + per-edge ordinal; reset lookback flags ---
        if (b == 0 && t < NBMAX) g_bflag[t] = 0;
        int e = b * 256 + t;
        if (e < E) {
            int d = __ldcs(dst + e);
            g_ord[e] = atomicAdd(&g_deg[d], 1);
        }
        __syncthreads();
        if (t == 0) { __threadfence(); atomicAdd(&g_hdone, 1); }
        return;
    }

    if (b < nhist + nscan) {
        // ---- phase 2: lookback scan of (deg+1) -> rowptr; re-zero deg ------
        if (t == 0) {
            while (*(volatile int*)&g_hdone < nhist) { }
            __threadfence();
        }
        __syncthreads();

        int sb = b - nhist;
        int i = sb * 256 + t;
        int v = 0;
        if (i < n) { v = g_deg[i] + 1; g_deg[i] = 0; }
        s[t] = v;
        __syncthreads();
#pragma unroll
        for (int off = 1; off < 256; off <<= 1) {
            int u = (t >= off) ? s[t - off] : 0;
            __syncthreads();
            s[t] += u;
            __syncthreads();
        }
        int incl = s[t];
        int agg  = s[255];
        if (t == 255) {
            g_bval[sb] = agg;
            __threadfence();
            g_bflag[sb] = 1;
        }
        int part = 0;
        for (int j = t; j < sb; j += 256) {
            while (g_bflag[j] == 0) { }
            part += *(volatile int*)&g_bval[j];
        }
        __syncthreads();
        s[t] = part;
        __syncthreads();
#pragma unroll
        for (int off = 128; off > 0; off >>= 1) {
            if (t < off) s[t] += s[t + off];
            __syncthreads();
        }
        int excl0 = s[0];
        if (i < n) g_rowptr[i] = excl0 + incl - v;
        if (sb == nscan - 1 && t == 255) g_rowptr[n] = excl0 + agg;
        __syncthreads();
        if (t == 0) { __threadfence(); atomicAdd(&g_sdone, 1); }
        return;
    }

    // ---- phase 3: atomic-free scatter ----
    if (t == 0) {
        while (*(volatile int*)&g_sdone < nscan) { }
        __threadfence();
    }
    __syncthreads();

    int e = (b - nhist - nscan) * 256 + t;
    int total = E + n;
    if (e >= total) return;
    if (e < E) {
        int d = __ldcs(dst + e);
        int p = g_rowptr[d] + __ldcs(g_ord + e);
        g_csr[p] = __ldcs(src + e);
    } else {
        int i = e - E;
        g_csr[g_rowptr[i + 1] - 1] = i;      // self loop in last slot
    }
}

// ---------------- aggregation: one warp per destination node ----------------
__global__ __launch_bounds__(256) void k_agg(
    const float* __restrict__ bias, float* __restrict__ out, int n)
{
    // reset fused-CSR phase counters for the next graph replay
    // (safe: this call's k_csr has fully completed — stream order)
    if (blockIdx.x == 0 && threadIdx.x == 0) { g_hdone = 0; g_sdone = 0; }

    int warp = (blockIdx.x * blockDim.x + threadIdx.x) >> 5;
    int lane = threadIdx.x & 31;
    if (warp >= n) return;
    int nd = warp;
    int h = lane >> 3;

    int begin = g_rowptr[nd], end = g_rowptr[nd + 1];
    float adh = g_adst[nd * 4 + h];

    unsigned long long acc01 = 0ull, acc23 = 0ull;   // packed f32x2 accumulators
    float den = 0.f;
    const float* xpb = g_xp + lane * 4;

    int i = begin;
    for (; i + 4 <= end; i += 4) {
        int s0 = g_csr[i], s1 = g_csr[i + 1], s2 = g_csr[i + 2], s3 = g_csr[i + 3];
        float a0 = g_asrc[s0 * 4 + h] + adh;
        float a1 = g_asrc[s1 * 4 + h] + adh;
        float a2 = g_asrc[s2 * 4 + h] + adh;
        float a3 = g_asrc[s3 * 4 + h] + adh;
        ulonglong2 u0 = *(const ulonglong2*)(xpb + (size_t)s0 * 128);
        ulonglong2 u1 = *(const ulonglong2*)(xpb + (size_t)s1 * 128);
        ulonglong2 u2 = *(const ulonglong2*)(xpb + (size_t)s2 * 128);
        ulonglong2 u3 = *(const ulonglong2*)(xpb + (size_t)s3 * 128);
        a0 = fmaxf(a0, NEG * a0);
        a1 = fmaxf(a1, NEG * a1);
        a2 = fmaxf(a2, NEG * a2);
        a3 = fmaxf(a3, NEG * a3);
        float w0 = ex2(a0), w1 = ex2(a1), w2 = ex2(a2), w3 = ex2(a3);
        unsigned long long ww;
        asm("mov.b64 %0, {%1, %1};" : "=l"(ww) : "f"(w0));
        ffma2(acc01, u0.x, ww); ffma2(acc23, u0.y, ww);
        asm("mov.b64 %0, {%1, %1};" : "=l"(ww) : "f"(w1));
        ffma2(acc01, u1.x, ww); ffma2(acc23, u1.y, ww);
        asm("mov.b64 %0, {%1, %1};" : "=l"(ww) : "f"(w2));
        ffma2(acc01, u2.x, ww); ffma2(acc23, u2.y, ww);
        asm("mov.b64 %0, {%1, %1};" : "=l"(ww) : "f"(w3));
        ffma2(acc01, u3.x, ww); ffma2(acc23, u3.y, ww);
        den += (w0 + w1) + (w2 + w3);
    }
    for (; i < end; i++) {
        int s0 = g_csr[i];
        float a0 = g_asrc[s0 * 4 + h] + adh;
        ulonglong2 u0 = *(const ulonglong2*)(xpb + (size_t)s0 * 128);
        a0 = fmaxf(a0, NEG * a0);
        float w0 = ex2(a0);
        unsigned long long ww;
        asm("mov.b64 %0, {%1, %1};" : "=l"(ww) : "f"(w0));
        ffma2(acc01, u0.x, ww); ffma2(acc23, u0.y, ww);
        den += w0;
    }

    float ax, ay, az, aw;
    asm("mov.b64 {%0, %1}, %2;" : "=f"(ax), "=f"(ay) : "l"(acc01));
    asm("mov.b64 {%0, %1}, %2;" : "=f"(az), "=f"(aw) : "l"(acc23));

    float inv = 1.0f / (den + 1e-16f);
    float4 bb = ((const float4*)bias)[lane];
    float4 o;
    o.x = ax * inv + bb.x;
    o.y = ay * inv + bb.y;
    o.z = az * inv + bb.z;
    o.w = aw * inv + bb.w;
    o.x = o.x > 0.f ? o.x : (__expf(o.x) - 1.f);
    o.y = o.y > 0.f ? o.y : (__expf(o.y) - 1.f);
    o.z = o.z > 0.f ? o.z : (__expf(o.z) - 1.f);
    o.w = o.w > 0.f ? o.w : (__expf(o.w) - 1.f);
    ((float4*)out)[(size_t)nd * 32 + lane] = o;
}

// ---------------- launch: GEMM overlapped with fused CSR build --------------
extern "C" void kernel_launch(void* const* d_in, const int* in_sizes, int n_in,
                              void* d_out, int out_size)
{
    const float* x    = (const float*)d_in[0];
    const float* W    = (const float*)d_in[1];
    const float* attS = (const float*)d_in[2];
    const float* attD = (const float*)d_in[3];
    const float* bias = (const float*)d_in[4];
    const int*   ei   = (const int*)d_in[5];

    int n = in_sizes[0] / FH;        // 50000
    int E = in_sizes[5] / 2;         // 800000
    const int* src = ei;
    const int* dst = ei + E;

    int nhist = (E + 255) / 256;                 // 3125
    int nscan = (n + 255) / 256;                 // 196
    int nscat = (E + n + 255) / 256;             // 3321

    // host-side resources, created once (host objects only; no device memory)
    static cudaStream_t s_side = nullptr;
    static cudaEvent_t  ev_fork = nullptr, ev_join = nullptr;
    if (s_side == nullptr) {
        cudaStreamCreateWithFlags(&s_side, cudaStreamNonBlocking);
        cudaEventCreateWithFlags(&ev_fork, cudaEventDisableTiming);
        cudaEventCreateWithFlags(&ev_join, cudaEventDisableTiming);
    }

    // fork: GEMM on side stream, fused CSR build on main stream
    cudaEventRecord(ev_fork, 0);
    cudaStreamWaitEvent(s_side, ev_fork, 0);
    k_gemm<<<(n + 127) / 128, 256, 0, s_side>>>(x, W, attS, attD, n);
    cudaEventRecord(ev_join, s_side);

    k_csr<<<nhist + nscan + nscat, 256>>>(src, dst, n, E, nhist, nscan);

    // join: aggregation needs both GEMM outputs and CSR
    cudaStreamWaitEvent(0, ev_join, 0);
    k_agg<<<(n * 32 + 255) / 256, 256>>>(bias, (float*)d_out, n);
}